// round 13
// baseline (speedup 1.0000x reference)
#include <cuda_runtime.h>
#include <cuda_fp16.h>
#include <cstdint>

// Problem: x [8,4096,512] f32, codebook [4096,512] f32
//   N = 32768 tokens, M = 4096 codes, K = 512
// Out (f32, concatenated): q_st [N*512], commitment_loss [N], cb_n [M*512]
//
// R13 two-pass scheme, int8 filter:
//   Pass 1: int8 IMMA GEMM (m16n8k32.s8 -> 2x MACs/instr vs fp16) on
//           per-row symmetric-quantized x and cb. int32 accumulate is EXACT;
//           only quantization error (~5.6e-4 cos sigma). Epilogue keeps
//           per-token TOP-2 approx-cos keys per 64-code group (32 MB).
//   Pass 2: per-token: max over 128 keys, exact fp32 rescore of all
//           candidates within TAU=8e-3 of max (~1.6/token), write outputs.
//   Exact rescore decides the winner -> rel_err identical to full-fp32.

#define NTOK   32768
#define MCODE  4096
#define KDIM   512
#define EPSN   1e-12f
#define TAU    8e-3f
#define NGRP   (MCODE / 64)                 // 64 groups per token

#define TILE        128
#define KCB         128                     // int8 per k-chunk (128 B rows)
#define NSTAGE      3
#define ATILE_BYTES (TILE * 128)            // 16384
#define STAGE_BYTES (2 * ATILE_BYTES)       // A + B
#define DYN_SMEM    (NSTAGE * STAGE_BYTES)  // 98304 -> 2 CTAs/SM
#define NITER       (KDIM / KCB)            // 4

// ---------------- device scratch (no allocs allowed) ----------------
__device__ int8_t             g_xq[(size_t)NTOK * KDIM];    // int8(x)     16 MB
__device__ int8_t             g_bq[(size_t)MCODE * KDIM];   // int8(cb)     2 MB
__device__ float              g_cbn[(size_t)MCODE * KDIM];  // normalized cb 8 MB
__device__ float              g_pa[NTOK];                   // (amax/126)*invnx
__device__ float              g_pb[MCODE];                  // (bmax/126)*invnb
__device__ float              g_invnx[NTOK];
__device__ unsigned long long g_cand[(size_t)NTOK * NGRP * 2];  // 32 MB

// ---------------- helpers ----------------
__device__ __forceinline__ uint32_t smem_u32(const void* p) {
    uint32_t a;
    asm("{ .reg .u64 t; cvta.to.shared.u64 t, %1; cvt.u32.u64 %0, t; }"
        : "=r"(a) : "l"(p));
    return a;
}
__device__ __forceinline__ void cp_async16(uint32_t s, const void* g) {
    asm volatile("cp.async.cg.shared.global [%0], [%1], 16;" :: "r"(s), "l"(g));
}
__device__ __forceinline__ void ldsm_x4(uint32_t* r, uint32_t addr) {
    asm volatile("ldmatrix.sync.aligned.m8n8.x4.shared.b16 {%0,%1,%2,%3}, [%4];"
                 : "=r"(r[0]), "=r"(r[1]), "=r"(r[2]), "=r"(r[3]) : "r"(addr));
}
__device__ __forceinline__ void mma16832s8(int* c, const uint32_t* a,
                                           const uint32_t* b) {
    asm volatile(
        "mma.sync.aligned.m16n8k32.row.col.s32.s8.s8.s32 "
        "{%0,%1,%2,%3}, {%4,%5,%6,%7}, {%8,%9}, {%0,%1,%2,%3};"
        : "+r"(c[0]), "+r"(c[1]), "+r"(c[2]), "+r"(c[3])
        : "r"(a[0]), "r"(a[1]), "r"(a[2]), "r"(a[3]), "r"(b[0]), "r"(b[1]));
}

// monotone float<->uint (order-preserving); key = (flipped score || ~idx)
__device__ __forceinline__ unsigned flip_f(unsigned fb) {
    return (fb & 0x80000000u) ? ~fb : (fb | 0x80000000u);
}
__device__ __forceinline__ unsigned unflip_f(unsigned u) {
    return (u & 0x80000000u) ? (u & 0x7FFFFFFFu) : ~u;
}
__device__ __forceinline__ unsigned long long make_key(unsigned fbits, int idx) {
    return (((unsigned long long)flip_f(fbits)) << 32) |
           (unsigned long long)(0xFFFFFFFFu - (unsigned)idx);
}
__device__ __forceinline__ float key_score(unsigned long long k) {
    return __uint_as_float(unflip_f((unsigned)(k >> 32)));
}
__device__ __forceinline__ int key_idx(unsigned long long k) {
    return (int)(0xFFFFFFFFu - (unsigned)(k & 0xFFFFFFFFull));
}
__device__ __forceinline__ int8_t q8(float v, float s) {
    return (int8_t)__float2int_rn(v * s);
}

// ---------------- kernel 1: cb norms + normalized copy + int8 quant ----------------
__global__ void norm_cb_kernel(const float* __restrict__ cb,
                               float* __restrict__ out_cb) {
    int row = blockIdx.x;
    int tid = threadIdx.x;   // 128 threads x 4 floats
    const float4 v = *(const float4*)(cb + (size_t)row * KDIM + tid * 4);
    float s = v.x * v.x + v.y * v.y + v.z * v.z + v.w * v.w;
    float m = fmaxf(fmaxf(fabsf(v.x), fabsf(v.y)), fmaxf(fabsf(v.z), fabsf(v.w)));
    #pragma unroll
    for (int off = 16; off > 0; off >>= 1) {
        s += __shfl_down_sync(~0u, s, off);
        m = fmaxf(m, __shfl_down_sync(~0u, m, off));
    }
    __shared__ float ws[4], wm[4];
    __shared__ float sinv, sqs;
    if ((tid & 31) == 0) { ws[tid >> 5] = s; wm[tid >> 5] = m; }
    __syncthreads();
    if (tid == 0) {
        float inv = 1.0f / fmaxf(sqrtf(ws[0] + ws[1] + ws[2] + ws[3]), EPSN);
        float mx = fmaxf(fmaxf(fmaxf(wm[0], wm[1]), fmaxf(wm[2], wm[3])), 1e-20f);
        sinv = inv;
        sqs = 126.0f / mx;
        g_pb[row] = (mx / 126.0f) * inv;
    }
    __syncthreads();
    float inv = sinv, qs = sqs;
    float o[4] = {v.x * inv, v.y * inv, v.z * inv, v.w * inv};
    size_t fb = (size_t)row * KDIM + tid * 4;
    *(float4*)(g_cbn + fb) = *(float4*)o;
    if (out_cb) *(float4*)(out_cb + fb) = *(float4*)o;
    char4 qv = make_char4(q8(v.x, qs), q8(v.y, qs), q8(v.z, qs), q8(v.w, qs));
    *(char4*)(g_bq + fb) = qv;
}

// ---------------- kernel 2: x inv-norms + int8 quant ----------------
__global__ void norm_x_kernel(const float* __restrict__ x) {
    int row = blockIdx.x;
    int tid = threadIdx.x;
    const float4 v = *(const float4*)(x + (size_t)row * KDIM + tid * 4);
    float s = v.x * v.x + v.y * v.y + v.z * v.z + v.w * v.w;
    float m = fmaxf(fmaxf(fabsf(v.x), fabsf(v.y)), fmaxf(fabsf(v.z), fabsf(v.w)));
    #pragma unroll
    for (int off = 16; off > 0; off >>= 1) {
        s += __shfl_down_sync(~0u, s, off);
        m = fmaxf(m, __shfl_down_sync(~0u, m, off));
    }
    __shared__ float ws[4], wm[4];
    __shared__ float sqs;
    if ((tid & 31) == 0) { ws[tid >> 5] = s; wm[tid >> 5] = m; }
    __syncthreads();
    if (tid == 0) {
        float inv = 1.0f / fmaxf(sqrtf(ws[0] + ws[1] + ws[2] + ws[3]), EPSN);
        float mx = fmaxf(fmaxf(fmaxf(wm[0], wm[1]), fmaxf(wm[2], wm[3])), 1e-20f);
        g_invnx[row] = inv;
        sqs = 126.0f / mx;
        g_pa[row] = (mx / 126.0f) * inv;
    }
    __syncthreads();
    float qs = sqs;
    char4 qv = make_char4(q8(v.x, qs), q8(v.y, qs), q8(v.z, qs), q8(v.w, qs));
    *(char4*)(g_xq + (size_t)row * KDIM + tid * 4) = qv;
}

// ---------------- kernel 3 (pass 1): int8 IMMA GEMM -> top-2 keys/group ----------------
// grid (MCODE/TILE=32 inner, NTOK/TILE=256); 256 threads; warp tile 32x64.
// SMEM rows are 128 B (= k128 int8); each mma consumes 32 B of k, 4 ks/chunk.
// Byte-level addressing identical to the proven fp16 path.
extern "C" __global__ void __launch_bounds__(256, 2)
vq_imma_kernel() {
    extern __shared__ char smem[];
    __shared__ float s_pb[TILE];
    __shared__ float s_pa[TILE];

    const int tid = threadIdx.x;
    const int wid = tid >> 5;
    const int lid = tid & 31;
    const int mBase = blockIdx.x * TILE;   // codes
    const int nBase = blockIdx.y * TILE;   // tokens

    if (tid < TILE) {
        s_pb[tid] = g_pb[mBase + tid];
        s_pa[tid] = g_pa[nBase + tid];
    }

    const uint32_t sbase = smem_u32(smem);

    // ---- cp.async coords: thread -> (row, 64B-half), 4x16B each op ----
    const int ldrow = tid >> 1;
    const int ldhalf = tid & 1;
    const int8_t* aSrc = g_xq + (size_t)(nBase + ldrow) * KDIM + ldhalf * 64;
    const int8_t* bSrc = g_bq + (size_t)(mBase + ldrow) * KDIM + ldhalf * 64;
    uint32_t aDst[4], bDst[4];
    {
        const uint32_t xr = (ldrow & 7) << 4;   // SW128 xor
        #pragma unroll
        for (int q = 0; q < 4; q++) {
            uint32_t cbyte = ldhalf * 64 + q * 16;
            uint32_t off = ldrow * 128 + (cbyte ^ xr);
            aDst[q] = off;
            bDst[q] = ATILE_BYTES + off;
        }
    }

    // ---- ldmatrix lane addressing (identical bytes to fp16 path) ----
    const int wRow = (wid & 3) * 32;   // token rows of this warp
    const int wCol = (wid >> 2) * 64;  // code cols of this warp
    uint32_t aRowOff[2], aXor[2];
    #pragma unroll
    for (int mt = 0; mt < 2; mt++) {
        int r = wRow + mt * 16 + (lid & 7) + ((lid >> 3) & 1) * 8;
        aRowOff[mt] = r * 128;
        aXor[mt] = (r & 7) << 4;
    }
    const uint32_t aCb = ((lid >> 4) & 1) * 16;
    uint32_t bRowOff[4], bXor[4];
    #pragma unroll
    for (int np = 0; np < 4; np++) {
        int r = wCol + np * 16 + (lid & 7) + ((lid >> 4) & 1) * 8;
        bRowOff[np] = ATILE_BYTES + r * 128;
        bXor[np] = (r & 7) << 4;
    }
    const uint32_t bCb = ((lid >> 3) & 1) * 16;

    int acc[2][8][4];
    #pragma unroll
    for (int mt = 0; mt < 2; mt++)
        #pragma unroll
        for (int nt = 0; nt < 8; nt++)
            #pragma unroll
            for (int j = 0; j < 4; j++) acc[mt][nt][j] = 0;

#define ISSUE(stage, bufi) do {                                           \
        uint32_t sb_ = sbase + (bufi) * STAGE_BYTES;                      \
        const int8_t* a_ = aSrc + (stage) * KCB;                          \
        const int8_t* b_ = bSrc + (stage) * KCB;                          \
        _Pragma("unroll")                                                 \
        for (int q = 0; q < 4; q++) cp_async16(sb_ + aDst[q], a_ + q * 16);\
        _Pragma("unroll")                                                 \
        for (int q = 0; q < 4; q++) cp_async16(sb_ + bDst[q], b_ + q * 16);\
    } while (0)

    // prologue: stages 0,1 in flight (buffers 0,1; buffer 2 free)
    ISSUE(0, 0);
    asm volatile("cp.async.commit_group;" ::: "memory");
    ISSUE(1, 1);
    asm volatile("cp.async.commit_group;" ::: "memory");

    int buf = 0;
    int ibuf = 2;
    for (int i = 0; i < NITER; i++) {
        asm volatile("cp.async.wait_group 1;" ::: "memory");
        __syncthreads();

        if (i + 2 < NITER) ISSUE(i + 2, ibuf);
        asm volatile("cp.async.commit_group;" ::: "memory");

        const uint32_t sb = sbase + buf * STAGE_BYTES;
        #pragma unroll
        for (int ks = 0; ks < 4; ks++) {     // 32 B of k per step
            uint32_t a[2][4];
            #pragma unroll
            for (int mt = 0; mt < 2; mt++)
                ldsm_x4(a[mt], sb + aRowOff[mt] + (((uint32_t)ks * 32 + aCb) ^ aXor[mt]));
            uint32_t b[4][4];
            #pragma unroll
            for (int np = 0; np < 4; np++)
                ldsm_x4(b[np], sb + bRowOff[np] + (((uint32_t)ks * 32 + bCb) ^ bXor[np]));
            #pragma unroll
            for (int mt = 0; mt < 2; mt++)
                #pragma unroll
                for (int nt = 0; nt < 8; nt++)
                    mma16832s8(acc[mt][nt], a[mt], &b[nt >> 1][(nt & 1) * 2]);
        }

        buf = (buf == NSTAGE - 1) ? 0 : buf + 1;
        ibuf = (ibuf == NSTAGE - 1) ? 0 : ibuf + 1;
    }

    // ---- epilogue: per-row top-2 keys over this warp's 64-code group ----
    const int g = blockIdx.x * 2 + (wid >> 2);   // 64-code group index
    #pragma unroll
    for (int mt = 0; mt < 2; mt++) {
        #pragma unroll
        for (int sub = 0; sub < 2; sub++) {
            const int rowLocal = wRow + mt * 16 + sub * 8 + (lid >> 2);
            const float pa = s_pa[rowLocal];
            unsigned long long t1 = 0ull, t2 = 0ull;
            #pragma unroll
            for (int nt = 0; nt < 8; nt++) {
                #pragma unroll
                for (int j = 0; j < 2; j++) {
                    const int cl = wCol + nt * 8 + 2 * (lid & 3) + j;
                    float f = __int2float_rn(acc[mt][nt][sub * 2 + j]) *
                              s_pb[cl] * pa;
                    unsigned long long k = make_key(__float_as_uint(f), mBase + cl);
                    if (k > t1) { t2 = t1; t1 = k; }
                    else if (k > t2) { t2 = k; }
                }
            }
            // merge top-2 across the 4 lanes of this row quad (xor 1, 2)
            #pragma unroll
            for (int off = 1; off <= 2; off <<= 1) {
                unsigned long long o1 = __shfl_xor_sync(~0u, t1, off);
                unsigned long long o2 = __shfl_xor_sync(~0u, t2, off);
                unsigned long long n1 = (t1 > o1) ? t1 : o1;
                unsigned long long lo = (t1 > o1) ? o1 : t1;
                unsigned long long n2 = (t2 > o2) ? t2 : o2;
                t1 = n1;
                t2 = (lo > n2) ? lo : n2;
            }
            if ((lid & 3) == 0) {
                size_t base = ((size_t)(nBase + rowLocal) * NGRP + g) * 2;
                g_cand[base]     = t1;
                g_cand[base + 1] = t2;
            }
        }
    }
}

// ---------------- kernel 4 (pass 2): max + exact rescore + output ----------------
// one block of 128 threads per token; reads 128 keys (1 KB)
extern "C" __global__ void __launch_bounds__(128)
select_kernel(const float* __restrict__ x,
              float* __restrict__ q_out, float* __restrict__ loss_out) {
    const int n = blockIdx.x;
    const int tid = threadIdx.x;
    const int lid = tid & 31;
    const int wid = tid >> 5;

    __shared__ float s_x[KDIM];
    __shared__ unsigned long long s_wmax[4];
    __shared__ int s_cand[64];
    __shared__ int s_cnt;
    __shared__ unsigned long long s_bestk;

    if (tid == 0) { s_cnt = 0; s_bestk = 0ull; }
    // x row -> smem (for exact dots)
    *(float4*)(s_x + tid * 4) = *(const float4*)(x + (size_t)n * KDIM + tid * 4);

    // each thread holds one key (128 = NGRP*2)
    const unsigned long long k = g_cand[(size_t)n * (NGRP * 2) + tid];

    // block max of keys
    unsigned long long mk = k;
    #pragma unroll
    for (int off = 16; off > 0; off >>= 1) {
        unsigned long long o = __shfl_xor_sync(~0u, mk, off);
        if (o > mk) mk = o;
    }
    if (lid == 0) s_wmax[wid] = mk;
    __syncthreads();
    unsigned long long bm = s_wmax[0];
    #pragma unroll
    for (int w = 1; w < 4; w++) if (s_wmax[w] > bm) bm = s_wmax[w];
    const float thr = key_score(bm) - TAU;

    // collect candidates within TAU of max
    if (key_score(k) >= thr) {
        int pos = atomicAdd(&s_cnt, 1);
        if (pos < 64) s_cand[pos] = key_idx(k);
    }
    __syncthreads();
    const int cnt = min(s_cnt, 64);

    // exact fp32 rescore: warp w handles candidates w, w+4, ...
    for (int c = wid; c < cnt; c += 4) {
        const int m = s_cand[c];
        const float* cbrow = g_cbn + (size_t)m * KDIM;
        float sum = 0.0f;
        #pragma unroll
        for (int e = 0; e < KDIM / 32; e++) {
            int kk = e * 32 + lid;
            sum = fmaf(s_x[kk], cbrow[kk], sum);
        }
        #pragma unroll
        for (int off = 16; off > 0; off >>= 1)
            sum += __shfl_xor_sync(~0u, sum, off);
        if (lid == 0)
            atomicMax(&s_bestk, make_key(__float_as_uint(sum), m));
    }
    __syncthreads();

    // output: q_st row (normalized codebook row) + commitment loss
    const unsigned long long pk = s_bestk;
    const unsigned idx = 0xFFFFFFFFu - (unsigned)(pk & 0xFFFFFFFFull);
    *(float4*)(q_out + (size_t)n * KDIM + tid * 4) =
        *(const float4*)(g_cbn + (size_t)idx * KDIM + tid * 4);
    if (tid == 0 && loss_out) {
        float dot = key_score(pk);          // exact x . cb_norm
        loss_out[n] = 1.0f - dot * g_invnx[n];
    }
}

// ---------------- host launch ----------------
extern "C" void kernel_launch(void* const* d_in, const int* in_sizes, int n_in,
                              void* d_out, int out_size) {
    const float* x  = (const float*)d_in[0];
    const float* cb = (const float*)d_in[1];
    const int N = in_sizes[0] / KDIM;   // 32768
    const int M = in_sizes[1] / KDIM;   // 4096

    float* out = (float*)d_out;
    float* q_out = out;
    float* loss_out = nullptr;
    float* cb_out = nullptr;
    long long need_full = (long long)N * KDIM + N + (long long)M * KDIM;
    if ((long long)out_size >= need_full) {
        loss_out = out + (size_t)N * KDIM;
        cb_out = loss_out + N;
    } else if ((long long)out_size >= (long long)N * KDIM + N) {
        loss_out = out + (size_t)N * KDIM;
    }

    cudaFuncSetAttribute(vq_imma_kernel,
                         cudaFuncAttributeMaxDynamicSharedMemorySize, DYN_SMEM);

    norm_cb_kernel<<<M, 128>>>(cb, cb_out);
    norm_x_kernel<<<N, 128>>>(x);

    dim3 grid(M / TILE, N / TILE);   // codes inner -> B (2 MB int8) hot in L2
    vq_imma_kernel<<<grid, 256, DYN_SMEM>>>();

    select_kernel<<<N, 128>>>(x, q_out, loss_out);
}

// round 14
// speedup vs baseline: 1.8565x; 1.8565x over previous
#include <cuda_runtime.h>
#include <cuda_fp16.h>
#include <cstdint>

// Problem: x [8,4096,512] f32, codebook [4096,512] f32
//   N = 32768 tokens, M = 4096 codes, K = 512
// Out (f32, concatenated): q_st [N*512], commitment_loss [N], cb_n [M*512]
//
// R14 = R12 with fp16-ACCUMULATOR HMMA (probe: consumer-style 2x rate?)
//   Pass 1: fp16 GEMM (K=512), fp16 acc; epilogue keeps per-token TOP-2
//           approx-cosine keys per 64-code group (128 keys/token, 32 MB).
//           fp16-acc adds ~2e-4 cos sigma -> TAU widened to 4e-3.
//   Pass 2: per-token: max over 128 keys, exact fp32 rescore of candidates
//           within TAU of max (~1.3/token), write q_st + loss.
//   Exact rescore decides the winner -> rel_err identical to full-fp32.

#define NTOK   32768
#define MCODE  4096
#define KDIM   512
#define EPSN   1e-12f
#define TAU    4e-3f
#define NGRP   (MCODE / 64)                 // 64 groups per token

#define TILE        128
#define KC          64                      // fp16 per k-chunk (128 B rows)
#define NSTAGE      3
#define ATILE_BYTES (TILE * 128)            // 16384
#define STAGE_BYTES (2 * ATILE_BYTES)       // A + B
#define DYN_SMEM    (NSTAGE * STAGE_BYTES)  // 98304 -> 2 CTAs/SM
#define NITER       (KDIM / KC)             // 8

// ---------------- device scratch (no allocs allowed) ----------------
__device__ __half             g_xs[(size_t)NTOK * KDIM];    // fp16(x)      32 MB
__device__ __half             g_bs[(size_t)MCODE * KDIM];   // fp16(raw cb)  4 MB
__device__ float              g_cbn[(size_t)MCODE * KDIM];  // normalized cb 8 MB
__device__ float              g_invnb[MCODE];
__device__ float              g_invnx[NTOK];
__device__ unsigned long long g_cand[(size_t)NTOK * NGRP * 2];  // 32 MB

// ---------------- helpers ----------------
__device__ __forceinline__ uint32_t smem_u32(const void* p) {
    uint32_t a;
    asm("{ .reg .u64 t; cvta.to.shared.u64 t, %1; cvt.u32.u64 %0, t; }"
        : "=r"(a) : "l"(p));
    return a;
}
__device__ __forceinline__ void cp_async16(uint32_t s, const void* g) {
    asm volatile("cp.async.cg.shared.global [%0], [%1], 16;" :: "r"(s), "l"(g));
}
__device__ __forceinline__ void ldsm_x4(uint32_t* r, uint32_t addr) {
    asm volatile("ldmatrix.sync.aligned.m8n8.x4.shared.b16 {%0,%1,%2,%3}, [%4];"
                 : "=r"(r[0]), "=r"(r[1]), "=r"(r[2]), "=r"(r[3]) : "r"(addr));
}
// fp16-accumulator HMMA: {c0,c1} half2 regs; c reg0 = row r cols(2j,2j+1),
// reg1 = row r+8 — same element positions as the f32 variant's c0..c3.
__device__ __forceinline__ void mma16816h(uint32_t* c, const uint32_t* a,
                                          const uint32_t* b) {
    asm volatile(
        "mma.sync.aligned.m16n8k16.row.col.f16.f16.f16.f16 "
        "{%0,%1}, {%2,%3,%4,%5}, {%6,%7}, {%0,%1};"
        : "+r"(c[0]), "+r"(c[1])
        : "r"(a[0]), "r"(a[1]), "r"(a[2]), "r"(a[3]), "r"(b[0]), "r"(b[1]));
}

// monotone float<->uint (order-preserving); key = (flipped score || ~idx)
__device__ __forceinline__ unsigned flip_f(unsigned fb) {
    return (fb & 0x80000000u) ? ~fb : (fb | 0x80000000u);
}
__device__ __forceinline__ unsigned unflip_f(unsigned u) {
    return (u & 0x80000000u) ? (u & 0x7FFFFFFFu) : ~u;
}
__device__ __forceinline__ unsigned long long make_key(unsigned fbits, int idx) {
    return (((unsigned long long)flip_f(fbits)) << 32) |
           (unsigned long long)(0xFFFFFFFFu - (unsigned)idx);
}
__device__ __forceinline__ float key_score(unsigned long long k) {
    return __uint_as_float(unflip_f((unsigned)(k >> 32)));
}
__device__ __forceinline__ int key_idx(unsigned long long k) {
    return (int)(0xFFFFFFFFu - (unsigned)(k & 0xFFFFFFFFull));
}

// ---------------- kernel 1: codebook norms + normalized copy + fp16 ----------------
__global__ void norm_cb_kernel(const float* __restrict__ cb,
                               float* __restrict__ out_cb) {
    int row = blockIdx.x;
    int tid = threadIdx.x;   // 128 threads x 4 floats
    const float4 v = *(const float4*)(cb + (size_t)row * KDIM + tid * 4);
    float s = v.x * v.x + v.y * v.y + v.z * v.z + v.w * v.w;
    #pragma unroll
    for (int off = 16; off > 0; off >>= 1) s += __shfl_down_sync(~0u, s, off);
    __shared__ float ws[4]; __shared__ float sinv;
    if ((tid & 31) == 0) ws[tid >> 5] = s;
    __syncthreads();
    if (tid == 0) {
        float inv = 1.0f / fmaxf(sqrtf(ws[0] + ws[1] + ws[2] + ws[3]), EPSN);
        sinv = inv;
        g_invnb[row] = inv;
    }
    __syncthreads();
    float inv = sinv;
    float o[4] = {v.x * inv, v.y * inv, v.z * inv, v.w * inv};
    size_t fb = (size_t)row * KDIM + tid * 4;
    *(float4*)(g_cbn + fb) = *(float4*)o;
    if (out_cb) *(float4*)(out_cb + fb) = *(float4*)o;
    // fp16 of RAW cb (GEMM operand; cosine scale applied in epilogue)
    __half h[4] = {__float2half_rn(v.x), __float2half_rn(v.y),
                   __float2half_rn(v.z), __float2half_rn(v.w)};
    *(uint2*)(g_bs + fb) = *(uint2*)h;
}

// ---------------- kernel 2: x inv-norms + fp16 ----------------
__global__ void norm_x_kernel(const float* __restrict__ x) {
    int row = blockIdx.x;
    int tid = threadIdx.x;
    const float4 v = *(const float4*)(x + (size_t)row * KDIM + tid * 4);
    float s = v.x * v.x + v.y * v.y + v.z * v.z + v.w * v.w;
    #pragma unroll
    for (int off = 16; off > 0; off >>= 1) s += __shfl_down_sync(~0u, s, off);
    __shared__ float ws[4];
    if ((tid & 31) == 0) ws[tid >> 5] = s;
    __syncthreads();
    if (tid == 0)
        g_invnx[row] = 1.0f / fmaxf(sqrtf(ws[0] + ws[1] + ws[2] + ws[3]), EPSN);
    __half h[4] = {__float2half_rn(v.x), __float2half_rn(v.y),
                   __float2half_rn(v.z), __float2half_rn(v.w)};
    *(uint2*)(g_xs + (size_t)row * KDIM + tid * 4) = *(uint2*)h;
}

// ---------------- kernel 3 (pass 1): fp16-acc HMMA GEMM -> top-2 keys/group ----------------
// grid (MCODE/TILE=32 inner, NTOK/TILE=256); 256 threads; warp tile 32x64.
extern "C" __global__ void __launch_bounds__(256, 2)
vq_hmma_kernel() {
    extern __shared__ char smem[];
    __shared__ float s_invb[TILE];
    __shared__ float s_invx[TILE];

    const int tid = threadIdx.x;
    const int wid = tid >> 5;
    const int lid = tid & 31;
    const int mBase = blockIdx.x * TILE;   // codes
    const int nBase = blockIdx.y * TILE;   // tokens

    if (tid < TILE) {
        s_invb[tid] = g_invnb[mBase + tid];
        s_invx[tid] = g_invnx[nBase + tid];
    }

    const uint32_t sbase = smem_u32(smem);

    // ---- cp.async coordinates: thread -> (row, 64B-half), 4x16B each op ----
    const int ldrow = tid >> 1;
    const int ldhalf = tid & 1;
    const __half* aSrc = g_xs + (size_t)(nBase + ldrow) * KDIM + ldhalf * 32;
    const __half* bSrc = g_bs + (size_t)(mBase + ldrow) * KDIM + ldhalf * 32;
    uint32_t aDst[4], bDst[4];
    {
        const uint32_t xr = (ldrow & 7) << 4;   // SW128 xor
        #pragma unroll
        for (int q = 0; q < 4; q++) {
            uint32_t cbyte = ldhalf * 64 + q * 16;
            uint32_t off = ldrow * 128 + (cbyte ^ xr);
            aDst[q] = off;
            bDst[q] = ATILE_BYTES + off;
        }
    }

    // ---- ldmatrix lane addressing ----
    const int wRow = (wid & 3) * 32;   // token rows of this warp
    const int wCol = (wid >> 2) * 64;  // code cols of this warp
    uint32_t aRowOff[2], aXor[2];
    #pragma unroll
    for (int mt = 0; mt < 2; mt++) {
        int r = wRow + mt * 16 + (lid & 7) + ((lid >> 3) & 1) * 8;
        aRowOff[mt] = r * 128;
        aXor[mt] = (r & 7) << 4;
    }
    const uint32_t aCb = ((lid >> 4) & 1) * 16;
    uint32_t bRowOff[4], bXor[4];
    #pragma unroll
    for (int np = 0; np < 4; np++) {
        int r = wCol + np * 16 + (lid & 7) + ((lid >> 4) & 1) * 8;
        bRowOff[np] = ATILE_BYTES + r * 128;
        bXor[np] = (r & 7) << 4;
    }
    const uint32_t bCb = ((lid >> 3) & 1) * 16;

    uint32_t acc[2][8][2];   // half2 accumulators
    #pragma unroll
    for (int mt = 0; mt < 2; mt++)
        #pragma unroll
        for (int nt = 0; nt < 8; nt++) {
            acc[mt][nt][0] = 0u;
            acc[mt][nt][1] = 0u;
        }

#define ISSUE(stage, bufi) do {                                           \
        uint32_t sb_ = sbase + (bufi) * STAGE_BYTES;                      \
        const __half* a_ = aSrc + (stage) * KC;                           \
        const __half* b_ = bSrc + (stage) * KC;                           \
        _Pragma("unroll")                                                 \
        for (int q = 0; q < 4; q++) cp_async16(sb_ + aDst[q], a_ + q * 8);\
        _Pragma("unroll")                                                 \
        for (int q = 0; q < 4; q++) cp_async16(sb_ + bDst[q], b_ + q * 8);\
    } while (0)

    // prologue: stages 0,1 in flight (buffers 0,1; buffer 2 free)
    ISSUE(0, 0);
    asm volatile("cp.async.commit_group;" ::: "memory");
    ISSUE(1, 1);
    asm volatile("cp.async.commit_group;" ::: "memory");

    int buf = 0;
    int ibuf = 2;
    for (int i = 0; i < NITER; i++) {
        asm volatile("cp.async.wait_group 1;" ::: "memory");
        __syncthreads();

        if (i + 2 < NITER) ISSUE(i + 2, ibuf);
        asm volatile("cp.async.commit_group;" ::: "memory");

        const uint32_t sb = sbase + buf * STAGE_BYTES;
        #pragma unroll
        for (int ks = 0; ks < 4; ks++) {
            uint32_t a[2][4];
            #pragma unroll
            for (int mt = 0; mt < 2; mt++)
                ldsm_x4(a[mt], sb + aRowOff[mt] + (((uint32_t)ks * 32 + aCb) ^ aXor[mt]));
            uint32_t b[4][4];
            #pragma unroll
            for (int np = 0; np < 4; np++)
                ldsm_x4(b[np], sb + bRowOff[np] + (((uint32_t)ks * 32 + bCb) ^ bXor[np]));
            #pragma unroll
            for (int mt = 0; mt < 2; mt++)
                #pragma unroll
                for (int nt = 0; nt < 8; nt++)
                    mma16816h(acc[mt][nt], a[mt], &b[nt >> 1][(nt & 1) * 2]);
        }

        buf = (buf == NSTAGE - 1) ? 0 : buf + 1;
        ibuf = (ibuf == NSTAGE - 1) ? 0 : ibuf + 1;
    }

    // ---- epilogue: per-row top-2 keys over this warp's 64-code group ----
    const int g = blockIdx.x * 2 + (wid >> 2);   // 64-code group index
    #pragma unroll
    for (int mt = 0; mt < 2; mt++) {
        #pragma unroll
        for (int sub = 0; sub < 2; sub++) {
            const int rowLocal = wRow + mt * 16 + sub * 8 + (lid >> 2);
            const float invx = s_invx[rowLocal];
            unsigned long long t1 = 0ull, t2 = 0ull;
            #pragma unroll
            for (int nt = 0; nt < 8; nt++) {
                const __half2 h2 = *(const __half2*)&acc[mt][nt][sub];
                const float2 f2 = __half22float2(h2);
                #pragma unroll
                for (int j = 0; j < 2; j++) {
                    const int cl = wCol + nt * 8 + 2 * (lid & 3) + j;
                    float f = (j ? f2.y : f2.x) * s_invb[cl] * invx;
                    unsigned long long k = make_key(__float_as_uint(f), mBase + cl);
                    if (k > t1) { t2 = t1; t1 = k; }
                    else if (k > t2) { t2 = k; }
                }
            }
            // merge top-2 across the 4 lanes of this row quad (xor 1, 2)
            #pragma unroll
            for (int off = 1; off <= 2; off <<= 1) {
                unsigned long long o1 = __shfl_xor_sync(~0u, t1, off);
                unsigned long long o2 = __shfl_xor_sync(~0u, t2, off);
                unsigned long long n1 = (t1 > o1) ? t1 : o1;
                unsigned long long lo = (t1 > o1) ? o1 : t1;
                unsigned long long n2 = (t2 > o2) ? t2 : o2;
                t1 = n1;
                t2 = (lo > n2) ? lo : n2;
            }
            if ((lid & 3) == 0) {
                size_t base = ((size_t)(nBase + rowLocal) * NGRP + g) * 2;
                g_cand[base]     = t1;
                g_cand[base + 1] = t2;
            }
        }
    }
}

// ---------------- kernel 4 (pass 2): max + exact rescore + output ----------------
// one block of 128 threads per token; reads 128 keys (1 KB)
extern "C" __global__ void __launch_bounds__(128)
select_kernel(const float* __restrict__ x,
              float* __restrict__ q_out, float* __restrict__ loss_out) {
    const int n = blockIdx.x;
    const int tid = threadIdx.x;
    const int lid = tid & 31;
    const int wid = tid >> 5;

    __shared__ float s_x[KDIM];
    __shared__ unsigned long long s_wmax[4];
    __shared__ int s_cand[64];
    __shared__ int s_cnt;
    __shared__ unsigned long long s_bestk;

    if (tid == 0) { s_cnt = 0; s_bestk = 0ull; }
    // x row -> smem (for exact dots)
    *(float4*)(s_x + tid * 4) = *(const float4*)(x + (size_t)n * KDIM + tid * 4);

    // each thread holds one key (128 = NGRP*2)
    const unsigned long long k = g_cand[(size_t)n * (NGRP * 2) + tid];

    // block max of keys
    unsigned long long mk = k;
    #pragma unroll
    for (int off = 16; off > 0; off >>= 1) {
        unsigned long long o = __shfl_xor_sync(~0u, mk, off);
        if (o > mk) mk = o;
    }
    if (lid == 0) s_wmax[wid] = mk;
    __syncthreads();
    unsigned long long bm = s_wmax[0];
    #pragma unroll
    for (int w = 1; w < 4; w++) if (s_wmax[w] > bm) bm = s_wmax[w];
    const float thr = key_score(bm) - TAU;

    // collect candidates within TAU of max
    if (key_score(k) >= thr) {
        int pos = atomicAdd(&s_cnt, 1);
        if (pos < 64) s_cand[pos] = key_idx(k);
    }
    __syncthreads();
    const int cnt = min(s_cnt, 64);

    // exact fp32 rescore: warp w handles candidates w, w+4, ...
    for (int c = wid; c < cnt; c += 4) {
        const int m = s_cand[c];
        const float* cbrow = g_cbn + (size_t)m * KDIM;
        float sum = 0.0f;
        #pragma unroll
        for (int e = 0; e < KDIM / 32; e++) {
            int kk = e * 32 + lid;
            sum = fmaf(s_x[kk], cbrow[kk], sum);
        }
        #pragma unroll
        for (int off = 16; off > 0; off >>= 1)
            sum += __shfl_xor_sync(~0u, sum, off);
        if (lid == 0)
            atomicMax(&s_bestk, make_key(__float_as_uint(sum), m));
    }
    __syncthreads();

    // output: q_st row (normalized codebook row) + commitment loss
    const unsigned long long pk = s_bestk;
    const unsigned idx = 0xFFFFFFFFu - (unsigned)(pk & 0xFFFFFFFFull);
    *(float4*)(q_out + (size_t)n * KDIM + tid * 4) =
        *(const float4*)(g_cbn + (size_t)idx * KDIM + tid * 4);
    if (tid == 0 && loss_out) {
        float dot = key_score(pk);          // exact x . cb_norm
        loss_out[n] = 1.0f - dot * g_invnx[n];
    }
}

// ---------------- host launch ----------------
extern "C" void kernel_launch(void* const* d_in, const int* in_sizes, int n_in,
                              void* d_out, int out_size) {
    const float* x  = (const float*)d_in[0];
    const float* cb = (const float*)d_in[1];
    const int N = in_sizes[0] / KDIM;   // 32768
    const int M = in_sizes[1] / KDIM;   // 4096

    float* out = (float*)d_out;
    float* q_out = out;
    float* loss_out = nullptr;
    float* cb_out = nullptr;
    long long need_full = (long long)N * KDIM + N + (long long)M * KDIM;
    if ((long long)out_size >= need_full) {
        loss_out = out + (size_t)N * KDIM;
        cb_out = loss_out + N;
    } else if ((long long)out_size >= (long long)N * KDIM + N) {
        loss_out = out + (size_t)N * KDIM;
    }

    cudaFuncSetAttribute(vq_hmma_kernel,
                         cudaFuncAttributeMaxDynamicSharedMemorySize, DYN_SMEM);

    norm_cb_kernel<<<M, 128>>>(cb, cb_out);
    norm_x_kernel<<<N, 128>>>(x);

    dim3 grid(M / TILE, N / TILE);   // codes inner -> B (4 MB fp16) hot in L2
    vq_hmma_kernel<<<grid, 256, DYN_SMEM>>>();

    select_kernel<<<N, 128>>>(x, q_out, loss_out);
}

// round 16
// speedup vs baseline: 1.8882x; 1.0171x over previous
#include <cuda_runtime.h>
#include <cuda_fp16.h>
#include <cstdint>

// Problem: x [8,4096,512] f32, codebook [4096,512] f32
//   N = 32768 tokens, M = 4096 codes, K = 512
// Out (f32, concatenated): q_st [N*512], commitment_loss [N], cb_n [M*512]
//
// R16 = R15 with the fast-path loss bug fixed:
//   filter keys store COSINE (already x invnx) -> fast-path loss is
//   1 - key_score(bm), NOT 1 - key_score*invnx (that was double-scaling).
//   Slow-path keys store raw dot x.cb_n -> those DO need *invnx.

#define NTOK   32768
#define MCODE  4096
#define KDIM   512
#define EPSN   1e-12f
#define TAU    1e-3f
#define NGRP   (MCODE / 64)                 // 64 groups per token

#define TILE        128
#define KC          64                      // fp16 per k-chunk (128 B rows)
#define NSTAGE      3
#define ATILE_BYTES (TILE * 128)            // 16384
#define STAGE_BYTES (2 * ATILE_BYTES)       // A + B
#define DYN_SMEM    (NSTAGE * STAGE_BYTES)  // 98304 -> 2 CTAs/SM
#define NITER       (KDIM / KC)             // 8

// ---------------- device scratch (no allocs allowed) ----------------
__device__ __half             g_xs[(size_t)NTOK * KDIM];    // fp16(x)      32 MB
__device__ __half             g_bs[(size_t)MCODE * KDIM];   // fp16(raw cb)  4 MB
__device__ float              g_cbn[(size_t)MCODE * KDIM];  // normalized cb 8 MB
__device__ float              g_invnb[MCODE];
__device__ float              g_invnx[NTOK];
__device__ unsigned long long g_cand[(size_t)NTOK * NGRP * 2];  // 32 MB

// ---------------- helpers ----------------
__device__ __forceinline__ uint32_t smem_u32(const void* p) {
    uint32_t a;
    asm("{ .reg .u64 t; cvta.to.shared.u64 t, %1; cvt.u32.u64 %0, t; }"
        : "=r"(a) : "l"(p));
    return a;
}
__device__ __forceinline__ void cp_async16(uint32_t s, const void* g) {
    asm volatile("cp.async.cg.shared.global [%0], [%1], 16;" :: "r"(s), "l"(g));
}
__device__ __forceinline__ void ldsm_x4(uint32_t* r, uint32_t addr) {
    asm volatile("ldmatrix.sync.aligned.m8n8.x4.shared.b16 {%0,%1,%2,%3}, [%4];"
                 : "=r"(r[0]), "=r"(r[1]), "=r"(r[2]), "=r"(r[3]) : "r"(addr));
}
__device__ __forceinline__ void mma16816(float* c, const uint32_t* a,
                                         const uint32_t* b) {
    asm volatile(
        "mma.sync.aligned.m16n8k16.row.col.f32.f16.f16.f32 "
        "{%0,%1,%2,%3}, {%4,%5,%6,%7}, {%8,%9}, {%0,%1,%2,%3};"
        : "+f"(c[0]), "+f"(c[1]), "+f"(c[2]), "+f"(c[3])
        : "r"(a[0]), "r"(a[1]), "r"(a[2]), "r"(a[3]), "r"(b[0]), "r"(b[1]));
}

// monotone float<->uint (order-preserving); key = (flipped score || ~idx)
__device__ __forceinline__ unsigned flip_f(unsigned fb) {
    return (fb & 0x80000000u) ? ~fb : (fb | 0x80000000u);
}
__device__ __forceinline__ unsigned unflip_f(unsigned u) {
    return (u & 0x80000000u) ? (u & 0x7FFFFFFFu) : ~u;
}
__device__ __forceinline__ unsigned long long make_key(unsigned fbits, int idx) {
    return (((unsigned long long)flip_f(fbits)) << 32) |
           (unsigned long long)(0xFFFFFFFFu - (unsigned)idx);
}
__device__ __forceinline__ float key_score(unsigned long long k) {
    return __uint_as_float(unflip_f((unsigned)(k >> 32)));
}
__device__ __forceinline__ int key_idx(unsigned long long k) {
    return (int)(0xFFFFFFFFu - (unsigned)(k & 0xFFFFFFFFull));
}

// ---------------- kernel 1: merged prep (cb rows then x rows) ----------------
// grid = MCODE + NTOK blocks of 128 threads.
__global__ void prep_kernel(const float* __restrict__ x,
                            const float* __restrict__ cb,
                            float* __restrict__ out_cb) {
    const int row = blockIdx.x;
    const int tid = threadIdx.x;
    __shared__ float ws[4];
    __shared__ float sinv;

    if (row < MCODE) {
        // ---- codebook row: norm + normalized copy + fp16 of raw ----
        const float4 v = *(const float4*)(cb + (size_t)row * KDIM + tid * 4);
        float s = v.x * v.x + v.y * v.y + v.z * v.z + v.w * v.w;
        #pragma unroll
        for (int off = 16; off > 0; off >>= 1) s += __shfl_down_sync(~0u, s, off);
        if ((tid & 31) == 0) ws[tid >> 5] = s;
        __syncthreads();
        if (tid == 0) {
            float inv = 1.0f / fmaxf(sqrtf(ws[0] + ws[1] + ws[2] + ws[3]), EPSN);
            sinv = inv;
            g_invnb[row] = inv;
        }
        __syncthreads();
        const float inv = sinv;
        float o[4] = {v.x * inv, v.y * inv, v.z * inv, v.w * inv};
        size_t fb = (size_t)row * KDIM + tid * 4;
        *(float4*)(g_cbn + fb) = *(float4*)o;
        if (out_cb) *(float4*)(out_cb + fb) = *(float4*)o;
        __half h[4] = {__float2half_rn(v.x), __float2half_rn(v.y),
                       __float2half_rn(v.z), __float2half_rn(v.w)};
        *(uint2*)(g_bs + fb) = *(uint2*)h;
    } else {
        // ---- x row: inv-norm + fp16 ----
        const int r = row - MCODE;
        const float4 v = *(const float4*)(x + (size_t)r * KDIM + tid * 4);
        float s = v.x * v.x + v.y * v.y + v.z * v.z + v.w * v.w;
        #pragma unroll
        for (int off = 16; off > 0; off >>= 1) s += __shfl_down_sync(~0u, s, off);
        if ((tid & 31) == 0) ws[tid >> 5] = s;
        __syncthreads();
        if (tid == 0)
            g_invnx[r] = 1.0f / fmaxf(sqrtf(ws[0] + ws[1] + ws[2] + ws[3]), EPSN);
        __half h[4] = {__float2half_rn(v.x), __float2half_rn(v.y),
                       __float2half_rn(v.z), __float2half_rn(v.w)};
        *(uint2*)(g_xs + (size_t)r * KDIM + tid * 4) = *(uint2*)h;
    }
}

// ---------------- kernel 2 (pass 1): fp16 HMMA GEMM -> top-2 keys/group ----------------
// grid (MCODE/TILE=32 inner, NTOK/TILE=256); 256 threads; warp tile 32x64.
extern "C" __global__ void __launch_bounds__(256, 2)
vq_hmma_kernel() {
    extern __shared__ char smem[];
    __shared__ float s_invb[TILE];
    __shared__ float s_invx[TILE];

    const int tid = threadIdx.x;
    const int wid = tid >> 5;
    const int lid = tid & 31;
    const int mBase = blockIdx.x * TILE;   // codes
    const int nBase = blockIdx.y * TILE;   // tokens

    if (tid < TILE) {
        s_invb[tid] = g_invnb[mBase + tid];
        s_invx[tid] = g_invnx[nBase + tid];
    }

    const uint32_t sbase = smem_u32(smem);

    // ---- cp.async coordinates: thread -> (row, 64B-half), 4x16B each op ----
    const int ldrow = tid >> 1;
    const int ldhalf = tid & 1;
    const __half* aSrc = g_xs + (size_t)(nBase + ldrow) * KDIM + ldhalf * 32;
    const __half* bSrc = g_bs + (size_t)(mBase + ldrow) * KDIM + ldhalf * 32;
    uint32_t aDst[4], bDst[4];
    {
        const uint32_t xr = (ldrow & 7) << 4;   // SW128 xor
        #pragma unroll
        for (int q = 0; q < 4; q++) {
            uint32_t cbyte = ldhalf * 64 + q * 16;
            uint32_t off = ldrow * 128 + (cbyte ^ xr);
            aDst[q] = off;
            bDst[q] = ATILE_BYTES + off;
        }
    }

    // ---- ldmatrix lane addressing ----
    const int wRow = (wid & 3) * 32;   // token rows of this warp
    const int wCol = (wid >> 2) * 64;  // code cols of this warp
    uint32_t aRowOff[2], aXor[2];
    #pragma unroll
    for (int mt = 0; mt < 2; mt++) {
        int r = wRow + mt * 16 + (lid & 7) + ((lid >> 3) & 1) * 8;
        aRowOff[mt] = r * 128;
        aXor[mt] = (r & 7) << 4;
    }
    const uint32_t aCb = ((lid >> 4) & 1) * 16;
    uint32_t bRowOff[4], bXor[4];
    #pragma unroll
    for (int np = 0; np < 4; np++) {
        int r = wCol + np * 16 + (lid & 7) + ((lid >> 4) & 1) * 8;
        bRowOff[np] = ATILE_BYTES + r * 128;
        bXor[np] = (r & 7) << 4;
    }
    const uint32_t bCb = ((lid >> 3) & 1) * 16;

    float acc[2][8][4];
    #pragma unroll
    for (int mt = 0; mt < 2; mt++)
        #pragma unroll
        for (int nt = 0; nt < 8; nt++)
            #pragma unroll
            for (int j = 0; j < 4; j++) acc[mt][nt][j] = 0.0f;

#define ISSUE(stage, bufi) do {                                           \
        uint32_t sb_ = sbase + (bufi) * STAGE_BYTES;                      \
        const __half* a_ = aSrc + (stage) * KC;                           \
        const __half* b_ = bSrc + (stage) * KC;                           \
        _Pragma("unroll")                                                 \
        for (int q = 0; q < 4; q++) cp_async16(sb_ + aDst[q], a_ + q * 8);\
        _Pragma("unroll")                                                 \
        for (int q = 0; q < 4; q++) cp_async16(sb_ + bDst[q], b_ + q * 8);\
    } while (0)

    // prologue: stages 0,1 in flight (buffers 0,1; buffer 2 free)
    ISSUE(0, 0);
    asm volatile("cp.async.commit_group;" ::: "memory");
    ISSUE(1, 1);
    asm volatile("cp.async.commit_group;" ::: "memory");

    int buf = 0;
    int ibuf = 2;
    for (int i = 0; i < NITER; i++) {
        asm volatile("cp.async.wait_group 1;" ::: "memory");
        __syncthreads();

        if (i + 2 < NITER) ISSUE(i + 2, ibuf);
        asm volatile("cp.async.commit_group;" ::: "memory");

        const uint32_t sb = sbase + buf * STAGE_BYTES;
        #pragma unroll
        for (int ks = 0; ks < 4; ks++) {
            uint32_t a[2][4];
            #pragma unroll
            for (int mt = 0; mt < 2; mt++)
                ldsm_x4(a[mt], sb + aRowOff[mt] + (((uint32_t)ks * 32 + aCb) ^ aXor[mt]));
            uint32_t b[4][4];
            #pragma unroll
            for (int np = 0; np < 4; np++)
                ldsm_x4(b[np], sb + bRowOff[np] + (((uint32_t)ks * 32 + bCb) ^ bXor[np]));
            #pragma unroll
            for (int mt = 0; mt < 2; mt++)
                #pragma unroll
                for (int nt = 0; nt < 8; nt++)
                    mma16816(acc[mt][nt], a[mt], &b[nt >> 1][(nt & 1) * 2]);
        }

        buf = (buf == NSTAGE - 1) ? 0 : buf + 1;
        ibuf = (ibuf == NSTAGE - 1) ? 0 : ibuf + 1;
    }

    // ---- epilogue: per-row top-2 COSINE keys over this warp's 64-code group ----
    const int g = blockIdx.x * 2 + (wid >> 2);   // 64-code group index
    #pragma unroll
    for (int mt = 0; mt < 2; mt++) {
        #pragma unroll
        for (int sub = 0; sub < 2; sub++) {
            const int rowLocal = wRow + mt * 16 + sub * 8 + (lid >> 2);
            const float invx = s_invx[rowLocal];
            unsigned long long t1 = 0ull, t2 = 0ull;
            #pragma unroll
            for (int nt = 0; nt < 8; nt++) {
                #pragma unroll
                for (int j = 0; j < 2; j++) {
                    const int cl = wCol + nt * 8 + 2 * (lid & 3) + j;
                    float f = acc[mt][nt][sub * 2 + j] * s_invb[cl] * invx;
                    unsigned long long k = make_key(__float_as_uint(f), mBase + cl);
                    if (k > t1) { t2 = t1; t1 = k; }
                    else if (k > t2) { t2 = k; }
                }
            }
            // merge top-2 across the 4 lanes of this row quad (xor 1, 2)
            #pragma unroll
            for (int off = 1; off <= 2; off <<= 1) {
                unsigned long long o1 = __shfl_xor_sync(~0u, t1, off);
                unsigned long long o2 = __shfl_xor_sync(~0u, t2, off);
                unsigned long long n1 = (t1 > o1) ? t1 : o1;
                unsigned long long lo = (t1 > o1) ? o1 : t1;
                unsigned long long n2 = (t2 > o2) ? t2 : o2;
                t1 = n1;
                t2 = (lo > n2) ? lo : n2;
            }
            if ((lid & 3) == 0) {
                size_t base = ((size_t)(nBase + rowLocal) * NGRP + g) * 2;
                g_cand[base]     = t1;
                g_cand[base + 1] = t2;
            }
        }
    }
}

// ---------------- kernel 3 (pass 2): max + fast path / exact rescore ----------------
// one block of 128 threads per token; reads 128 keys (1 KB)
extern "C" __global__ void __launch_bounds__(128)
select_kernel(const float* __restrict__ x,
              float* __restrict__ q_out, float* __restrict__ loss_out) {
    const int n = blockIdx.x;
    const int tid = threadIdx.x;
    const int lid = tid & 31;
    const int wid = tid >> 5;

    __shared__ float s_x[KDIM];
    __shared__ unsigned long long s_wmax[4];
    __shared__ int s_cand[64];
    __shared__ int s_cnt;
    __shared__ unsigned long long s_bestk;

    if (tid == 0) { s_cnt = 0; s_bestk = 0ull; }

    // each thread holds one key (128 = NGRP*2); keys score = approx COSINE
    const unsigned long long k = g_cand[(size_t)n * (NGRP * 2) + tid];

    // block max of keys
    unsigned long long mk = k;
    #pragma unroll
    for (int off = 16; off > 0; off >>= 1) {
        unsigned long long o = __shfl_xor_sync(~0u, mk, off);
        if (o > mk) mk = o;
    }
    if (lid == 0) s_wmax[wid] = mk;
    __syncthreads();
    unsigned long long bm = s_wmax[0];
    #pragma unroll
    for (int w = 1; w < 4; w++) if (s_wmax[w] > bm) bm = s_wmax[w];
    const float thr = key_score(bm) - TAU;

    const int pred = (key_score(k) >= thr) ? 1 : 0;
    const int cnt = __syncthreads_count(pred);

    unsigned idx;
    if (cnt == 1) {
        // ---- fast path (~93%): unique candidate; filter cosine decides ----
        idx = (unsigned)key_idx(bm);
        if (tid == 0 && loss_out)
            loss_out[n] = 1.0f - key_score(bm);   // key IS cosine (bug fixed)
    } else {
        // ---- slow path: exact fp32 rescore of all within-TAU candidates ----
        if (pred) {
            int pos = atomicAdd(&s_cnt, 1);
            if (pos < 64) s_cand[pos] = key_idx(k);
        }
        // x row -> smem (only needed here)
        *(float4*)(s_x + tid * 4) = *(const float4*)(x + (size_t)n * KDIM + tid * 4);
        __syncthreads();
        const int c_n = min(s_cnt, 64);
        for (int c = wid; c < c_n; c += 4) {
            const int m = s_cand[c];
            const float* cbrow = g_cbn + (size_t)m * KDIM;
            float sum = 0.0f;
            #pragma unroll
            for (int e = 0; e < KDIM / 32; e++) {
                int kk = e * 32 + lid;
                sum = fmaf(s_x[kk], cbrow[kk], sum);
            }
            #pragma unroll
            for (int off = 16; off > 0; off >>= 1)
                sum += __shfl_xor_sync(~0u, sum, off);
            if (lid == 0)
                atomicMax(&s_bestk, make_key(__float_as_uint(sum), m));
        }
        __syncthreads();
        const unsigned long long pk = s_bestk;
        idx = 0xFFFFFFFFu - (unsigned)(pk & 0xFFFFFFFFull);
        if (tid == 0 && loss_out)
            loss_out[n] = 1.0f - key_score(pk) * g_invnx[n];  // dot -> cosine
    }

    // output: q_st row = normalized codebook row of the winner
    *(float4*)(q_out + (size_t)n * KDIM + tid * 4) =
        *(const float4*)(g_cbn + (size_t)idx * KDIM + tid * 4);
}

// ---------------- host launch ----------------
extern "C" void kernel_launch(void* const* d_in, const int* in_sizes, int n_in,
                              void* d_out, int out_size) {
    const float* x  = (const float*)d_in[0];
    const float* cb = (const float*)d_in[1];
    const int N = in_sizes[0] / KDIM;   // 32768
    const int M = in_sizes[1] / KDIM;   // 4096

    float* out = (float*)d_out;
    float* q_out = out;
    float* loss_out = nullptr;
    float* cb_out = nullptr;
    long long need_full = (long long)N * KDIM + N + (long long)M * KDIM;
    if ((long long)out_size >= need_full) {
        loss_out = out + (size_t)N * KDIM;
        cb_out = loss_out + N;
    } else if ((long long)out_size >= (long long)N * KDIM + N) {
        loss_out = out + (size_t)N * KDIM;
    }

    cudaFuncSetAttribute(vq_hmma_kernel,
                         cudaFuncAttributeMaxDynamicSharedMemorySize, DYN_SMEM);

    prep_kernel<<<M + N, 128>>>(x, cb, cb_out);

    dim3 grid(M / TILE, N / TILE);   // codes inner -> B (4 MB fp16) hot in L2
    vq_hmma_kernel<<<grid, 256, DYN_SMEM>>>();

    select_kernel<<<N, 128>>>(x, q_out, loss_out);
}